// round 17
// baseline (speedup 1.0000x reference)
#include <cuda_runtime.h>

#define Hh 256
#define Tt 187
#define Bb 1024
#define Cc 5
#define MB 8
#define NCTA (Bb / MB)   // 128 CTAs, 1 per SM
#define THR 512          // warps 0-7 = layer0 chain (A), 8-15 = layer1 chain (B)

// Packed weights: [k/4][j][4] so lane j loads 16B of 4 consecutive k's,
// coalesced across lanes (lanes = consecutive j).
__device__ float g_Wp0[Hh * Hh];
__device__ float g_Wpih1[Hh * Hh];
__device__ float g_Wp1[Hh * Hh];

__global__ void pack_kernel(const float* __restrict__ W_hh0,
                            const float* __restrict__ W_ih1,
                            const float* __restrict__ W_hh1) {
    int j = blockIdx.x, k = threadIdx.x;
    int src = j * Hh + k;
    int dst = ((k >> 2) * Hh + j) * 4 + (k & 3);
    g_Wp0[dst]   = W_hh0[src];
    g_Wpih1[dst] = W_ih1[src];
    g_Wp1[dst]   = W_hh1[src];
}

union F2U { unsigned long long u; float2 f; };

__device__ __forceinline__ unsigned long long f32x2_fma(
    unsigned long long a, unsigned long long b, unsigned long long c) {
    unsigned long long d;
    asm("fma.rn.f32x2 %0, %1, %2, %3;" : "=l"(d) : "l"(a), "l"(b), "l"(c));
    return d;
}

__device__ __forceinline__ void bar_sync(int id, int cnt) {
    asm volatile("bar.sync %0, %1;" :: "r"(id), "r"(cnt) : "memory");
}
__device__ __forceinline__ void bar_arrive(int id, int cnt) {
    asm volatile("bar.arrive %0, %1;" :: "r"(id), "r"(cnt) : "memory");
}

// Named barrier ids (0 reserved for __syncthreads)
#define BAR_A      1   // A-internal, 256
#define BAR_B      2   // B-internal, 256
#define BAR_FULL0  4   // h0 buf0 produced  (A arrives, B syncs; 512)
#define BAR_FULL1  5
#define BAR_EMPTY0 6   // h0 buf0 consumed  (B arrives, A syncs; 512)
#define BAR_EMPTY1 7

struct Smem {
    float pA[4][MB][Hh];         // 32 KB  layer0 partials [kg][row][col]
    float pB[4][MB][Hh];         // 32 KB  layer1 partials
    float h0[2][MB][Hh];         // 16 KB  double-buffered h0 (A->B handoff)
    float h1[MB][Hh];            // 8 KB   (B-private, in-place)
    float xs[MB][Tt + 1];        // ~6 KB
    float wih0s[Hh], bias0s[Hh], bias1s[Hh];   // 3 KB
};                               // ~97 KB

__global__ void __launch_bounds__(THR, 1) rnn_pipe_kernel(
    const float* __restrict__ x,
    const float* __restrict__ W_ih0,
    const float* __restrict__ b_ih0, const float* __restrict__ b_hh0,
    const float* __restrict__ b_ih1, const float* __restrict__ b_hh1,
    const float* __restrict__ W_fc,  const float* __restrict__ b_fc,
    float* __restrict__ out)
{
    extern __shared__ __align__(16) char raw[];
    Smem& S = *reinterpret_cast<Smem*>(raw);

    const int t    = threadIdx.x;
    const int lane = t & 31;
    const int w    = t >> 5;
    const int b0   = blockIdx.x * MB;

    // ---- staging (all 512 threads) --------------------------------------
    for (int i = t; i < MB * Tt; i += THR) {
        int r = i / Tt, c = i % Tt;
        S.xs[r][c] = x[(b0 + r) * Tt + c];
    }
    for (int i = t; i < Hh; i += THR) {
        S.wih0s[i]  = W_ih0[i];
        S.bias0s[i] = b_ih0[i] + b_hh0[i];
        S.bias1s[i] = b_ih1[i] + b_hh1[i];
    }
    for (int i = t; i < MB * Hh; i += THR) {
        (&S.h0[0][0][0])[i] = 0.f;
        (&S.h0[1][0][0])[i] = 0.f;
        (&S.h1[0][0])[i]    = 0.f;
    }
    __syncthreads();

    if (w < 8) {
        // ================= GROUP A: layer-0 recurrence ====================
        const int cg   = w & 1;
        const int kg   = w >> 1;            // 0..3
        const int c0   = cg * 128 + lane;   // cols c0 + {0,32,64,96}
        const int k4lo = kg * 16;
        const int tA   = t;                  // 0..255; reducer col = tA
        const float wih0r  = S.wih0s[tA];
        const float bias0r = S.bias0s[tA];

        for (int step = 0; step < Tt; ++step) {
            const int p = step & 1;
            // partials: read h0[1-p] (previous h0)
            unsigned long long acc[MB][4];
            #pragma unroll
            for (int r = 0; r < MB; ++r)
                #pragma unroll
                for (int c = 0; c < 4; ++c) acc[r][c] = 0ULL;

            #pragma unroll 4
            for (int kk = 0; kk < 16; ++kk) {
                const int k4 = k4lo + kk;
                ulonglong2 wv[4];
                #pragma unroll
                for (int c = 0; c < 4; ++c)
                    wv[c] = *reinterpret_cast<const ulonglong2*>(
                        &g_Wp0[(k4 * Hh + c0 + 32 * c) * 4]);
                #pragma unroll
                for (int r = 0; r < MB; ++r) {
                    ulonglong2 h = *reinterpret_cast<const ulonglong2*>(
                        &S.h0[1 - p][r][k4 * 4]);
                    #pragma unroll
                    for (int c = 0; c < 4; ++c) {
                        acc[r][c] = f32x2_fma(h.x, wv[c].x, acc[r][c]);
                        acc[r][c] = f32x2_fma(h.y, wv[c].y, acc[r][c]);
                    }
                }
            }
            #pragma unroll
            for (int r = 0; r < MB; ++r)
                #pragma unroll
                for (int c = 0; c < 4; ++c) {
                    F2U u; u.u = acc[r][c];
                    S.pA[kg][r][c0 + 32 * c] = u.f.x + u.f.y;
                }
            bar_sync(BAR_A, 256);                 // partials visible in A
            bar_sync(p ? BAR_EMPTY1 : BAR_EMPTY0, 512);  // buf p free

            // reduce + tanh -> h0[p], one column per thread, 8 rows
            #pragma unroll
            for (int r = 0; r < MB; ++r) {
                float s = (S.pA[0][r][tA] + S.pA[1][r][tA])
                        + (S.pA[2][r][tA] + S.pA[3][r][tA]);
                float pre = S.xs[r][step] * wih0r + bias0r + s;
                S.h0[p][r][tA] = tanhf(pre);
            }
            bar_sync(BAR_A, 256);                 // h0[p] fully written
            bar_arrive(p ? BAR_FULL1 : BAR_FULL0, 512);   // publish to B
        }
    } else {
        // ================= GROUP B: layer-1 recurrence ====================
        const int wb   = w - 8;
        const int cg   = wb & 1;
        const int kg   = wb >> 1;
        const int c0   = cg * 128 + lane;
        const int k4lo = kg * 16;
        const int tB   = t - 256;            // 0..255; reducer col = tB
        const float bias1r = S.bias1s[tB];

        // prime both h0 buffers as EMPTY
        bar_arrive(BAR_EMPTY0, 512);
        bar_arrive(BAR_EMPTY1, 512);

        for (int step = 0; step < Tt; ++step) {
            const int p = step & 1;
            bar_sync(p ? BAR_FULL1 : BAR_FULL0, 512);    // h0[p] ready

            unsigned long long acc[MB][4];
            #pragma unroll
            for (int r = 0; r < MB; ++r)
                #pragma unroll
                for (int c = 0; c < 4; ++c) acc[r][c] = 0ULL;

            #pragma unroll 2
            for (int kk = 0; kk < 16; ++kk) {
                const int k4 = k4lo + kk;
                ulonglong2 wa[4], wbv[4];
                #pragma unroll
                for (int c = 0; c < 4; ++c) {
                    wa[c]  = *reinterpret_cast<const ulonglong2*>(
                        &g_Wpih1[(k4 * Hh + c0 + 32 * c) * 4]);
                    wbv[c] = *reinterpret_cast<const ulonglong2*>(
                        &g_Wp1[(k4 * Hh + c0 + 32 * c) * 4]);
                }
                #pragma unroll
                for (int r = 0; r < MB; ++r) {
                    ulonglong2 ha = *reinterpret_cast<const ulonglong2*>(
                        &S.h0[p][r][k4 * 4]);
                    ulonglong2 hb = *reinterpret_cast<const ulonglong2*>(
                        &S.h1[r][k4 * 4]);
                    #pragma unroll
                    for (int c = 0; c < 4; ++c) {
                        acc[r][c] = f32x2_fma(ha.x, wa[c].x,  acc[r][c]);
                        acc[r][c] = f32x2_fma(ha.y, wa[c].y,  acc[r][c]);
                        acc[r][c] = f32x2_fma(hb.x, wbv[c].x, acc[r][c]);
                        acc[r][c] = f32x2_fma(hb.y, wbv[c].y, acc[r][c]);
                    }
                }
            }
            #pragma unroll
            for (int r = 0; r < MB; ++r)
                #pragma unroll
                for (int c = 0; c < 4; ++c) {
                    F2U u; u.u = acc[r][c];
                    S.pB[kg][r][c0 + 32 * c] = u.f.x + u.f.y;
                }
            bar_sync(BAR_B, 256);                 // h0[p]/h1 reads done
            bar_arrive(p ? BAR_EMPTY1 : BAR_EMPTY0, 512);  // release buf p

            // reduce + tanh -> h1 (in place)
            #pragma unroll
            for (int r = 0; r < MB; ++r) {
                float s = (S.pB[0][r][tB] + S.pB[1][r][tB])
                        + (S.pB[2][r][tB] + S.pB[3][r][tB]);
                S.h1[r][tB] = tanhf(bias1r + s);
            }
            bar_sync(BAR_B, 256);                 // h1 coherent for next step
        }
    }

    __syncthreads();

    // ---- final FC: out[b] = h1_last @ W_fc^T + b_fc ---------------------
    if (t < Cc * MB) {
        int c = t / MB, b = t % MB;
        float s = b_fc[c];
        #pragma unroll 8
        for (int h = 0; h < Hh; ++h)
            s += S.h1[b][h] * W_fc[c * Hh + h];
        out[(b0 + b) * Cc + c] = s;
    }
}

extern "C" void kernel_launch(void* const* d_in, const int* in_sizes, int n_in,
                              void* d_out, int out_size) {
    const float* x     = (const float*)d_in[0];
    const float* W_ih0 = (const float*)d_in[1];
    const float* W_hh0 = (const float*)d_in[2];
    const float* b_ih0 = (const float*)d_in[3];
    const float* b_hh0 = (const float*)d_in[4];
    const float* W_ih1 = (const float*)d_in[5];
    const float* W_hh1 = (const float*)d_in[6];
    const float* b_ih1 = (const float*)d_in[7];
    const float* b_hh1 = (const float*)d_in[8];
    const float* W_fc  = (const float*)d_in[9];
    const float* b_fc  = (const float*)d_in[10];
    float* out = (float*)d_out;

    cudaFuncSetAttribute(rnn_pipe_kernel,
                         cudaFuncAttributeMaxDynamicSharedMemorySize,
                         (int)sizeof(Smem));
    pack_kernel<<<Hh, Hh>>>(W_hh0, W_ih1, W_hh1);
    rnn_pipe_kernel<<<NCTA, THR, sizeof(Smem)>>>(
        x, W_ih0, b_ih0, b_hh0, b_ih1, b_hh1, W_fc, b_fc, out);
}